// round 1
// baseline (speedup 1.0000x reference)
#include <cuda_runtime.h>
#include <cuda_bf16.h>
#include <stdint.h>

// Problem constants
#define SEQ   4096
#define BS    4
#define SIZE  1024
#define NROWS (SEQ * BS)     // 16384
#define NDROP 409            // max(1, int(4096 * 0.1))

// Scratch (device globals: no allocation allowed in kernel_launch)
__device__ float g_key[BS * SEQ];    // key[b][s] = gumbel - w
__device__ float g_mask[BS * SEQ];   // 1.0 keep, 0.0 drop

// ---------------------------------------------------------------------------
// K1: w[b,s] = dot(h[s,b,:], emb); key = gumbel(u[b,s]) - w.  One warp per row.
// ---------------------------------------------------------------------------
__global__ void k_dot(const float* __restrict__ h,
                      const float* __restrict__ emb,
                      const float* __restrict__ gu)
{
    int gwarp = (blockIdx.x * blockDim.x + threadIdx.x) >> 5;
    int lane  = threadIdx.x & 31;
    if (gwarp >= NROWS) return;

    const float4* hr = reinterpret_cast<const float4*>(h + (size_t)gwarp * SIZE);
    const float4* e4 = reinterpret_cast<const float4*>(emb);

    float acc = 0.f;
    #pragma unroll
    for (int i = 0; i < 8; i++) {
        float4 a = __ldg(&hr[lane + i * 32]);
        float4 b = __ldg(&e4[lane + i * 32]);
        acc += a.x * b.x + a.y * b.y + a.z * b.z + a.w * b.w;
    }
    #pragma unroll
    for (int o = 16; o; o >>= 1) acc += __shfl_xor_sync(0xFFFFFFFFu, acc, o);

    if (lane == 0) {
        int s = gwarp >> 2;          // row = s*BS + b
        int b = gwarp & 3;
        float u = gu[b * SEQ + s];
        float gum = -logf(-logf(u + 1e-20f) + 1e-20f);
        g_key[b * SEQ + s] = gum - acc;
    }
}

// ---------------------------------------------------------------------------
// K2: per-batch radix select of the 409th largest key; build mask with exact
// JAX top_k tie-break (lowest index wins among equals). 1 block per batch.
// ---------------------------------------------------------------------------
__global__ void k_select()
{
    __shared__ unsigned su[SEQ];
    __shared__ int cnt;
    const int b = blockIdx.x;
    const int t = threadIdx.x;           // 512 threads

    // order-preserving float -> uint map (ascending)
    for (int i = t; i < SEQ; i += 512) {
        unsigned u = __float_as_uint(g_key[b * SEQ + i]);
        su[i] = (u & 0x80000000u) ? ~u : (u | 0x80000000u);
    }
    __syncthreads();

    unsigned prefix = 0;
    int k = NDROP;                       // k-th largest
    for (int bit = 31; bit >= 0; bit--) {
        if (t == 0) cnt = 0;
        __syncthreads();
        unsigned mask = (bit == 31) ? (1u << 31)
                                    : ((0xFFFFFFFFu << (bit + 1)) | (1u << bit));
        unsigned want = prefix | (1u << bit);
        int local = 0;
        for (int i = t; i < SEQ; i += 512)
            if ((su[i] & mask) == want) local++;
        atomicAdd(&cnt, local);
        __syncthreads();
        int c1 = cnt;
        if (c1 >= k) prefix |= (1u << bit);
        else         k -= c1;
        __syncthreads();
    }
    // prefix == su-value of the 409th largest

    // count strictly greater
    if (t == 0) cnt = 0;
    __syncthreads();
    int loc = 0;
    for (int i = t; i < SEQ; i += 512)
        if (su[i] > prefix) loc++;
    atomicAdd(&cnt, loc);
    __syncthreads();
    const int cg = cnt;

    for (int i = t; i < SEQ; i += 512)
        g_mask[b * SEQ + i] = (su[i] > prefix) ? 0.f : 1.f;
    __syncthreads();

    if (t == 0) {
        int need = NDROP - cg;           // ties to drop, lowest index first
        for (int i = 0; i < SEQ && need > 0; i++) {
            if (su[i] == prefix) { g_mask[b * SEQ + i] = 0.f; need--; }
        }
    }
}

// ---------------------------------------------------------------------------
// K3: y = x + h*mask; LayerNorm over last dim (1024), eps=1e-12.
// One 256-thread block per row; float4 per thread.
// ---------------------------------------------------------------------------
__global__ void k_ln(const float* __restrict__ x,
                     const float* __restrict__ h,
                     const float* __restrict__ gamma,
                     const float* __restrict__ beta,
                     float* __restrict__ out)
{
    const int r = blockIdx.x;            // row = s*BS + b
    const int s = r >> 2;
    const int b = r & 3;
    const float m = g_mask[b * SEQ + s];

    const size_t base = (size_t)r * SIZE;
    const int t = threadIdx.x;           // 256 threads, 4 floats each

    float4 xv = __ldg(&reinterpret_cast<const float4*>(x + base)[t]);
    float4 hv = __ldg(&reinterpret_cast<const float4*>(h + base)[t]);
    float4 y;
    y.x = xv.x + hv.x * m;
    y.y = xv.y + hv.y * m;
    y.z = xv.z + hv.z * m;
    y.w = xv.w + hv.w * m;

    float sum = y.x + y.y + y.z + y.w;
    float sq  = y.x * y.x + y.y * y.y + y.z * y.z + y.w * y.w;

    #pragma unroll
    for (int o = 16; o; o >>= 1) {
        sum += __shfl_xor_sync(0xFFFFFFFFu, sum, o);
        sq  += __shfl_xor_sync(0xFFFFFFFFu, sq,  o);
    }

    __shared__ float red[18];
    const int wid  = t >> 5;
    const int lane = t & 31;
    if (lane == 0) { red[wid] = sum; red[8 + wid] = sq; }
    __syncthreads();
    if (t == 0) {
        float S = 0.f, Q = 0.f;
        #pragma unroll
        for (int i = 0; i < 8; i++) { S += red[i]; Q += red[8 + i]; }
        float mu  = S * (1.f / SIZE);
        float var = Q * (1.f / SIZE) - mu * mu;
        red[16] = mu;
        red[17] = rsqrtf(var + 1e-12f);
    }
    __syncthreads();
    const float mu   = red[16];
    const float rstd = red[17];

    float4 g4 = __ldg(&reinterpret_cast<const float4*>(gamma)[t]);
    float4 b4 = __ldg(&reinterpret_cast<const float4*>(beta)[t]);
    float4 o;
    o.x = (y.x - mu) * rstd * g4.x + b4.x;
    o.y = (y.y - mu) * rstd * g4.y + b4.y;
    o.z = (y.z - mu) * rstd * g4.z + b4.z;
    o.w = (y.w - mu) * rstd * g4.w + b4.w;
    reinterpret_cast<float4*>(out + base)[t] = o;
}

// ---------------------------------------------------------------------------
extern "C" void kernel_launch(void* const* d_in, const int* in_sizes, int n_in,
                              void* d_out, int out_size)
{
    const float* x     = (const float*)d_in[0];  // (seq, bs, size)
    const float* h     = (const float*)d_in[1];  // (seq, bs, size)
    const float* emb   = (const float*)d_in[2];  // (size,)
    const float* gamma = (const float*)d_in[3];  // (size,)
    const float* beta  = (const float*)d_in[4];  // (size,)
    const float* gu    = (const float*)d_in[5];  // (bs, seq)
    // d_in[6] = lengths: unused by the reference
    float* out = (float*)d_out;

    // K1: 16384 warps, 8 warps/block
    k_dot<<<NROWS / 8, 256>>>(h, emb, gu);
    // K2: one block per batch
    k_select<<<BS, 512>>>();
    // K3: one block per row
    k_ln<<<NROWS, 256>>>(x, h, gamma, beta, out);
}

// round 2
// speedup vs baseline: 4.1571x; 4.1571x over previous
#include <cuda_runtime.h>
#include <cuda_bf16.h>
#include <stdint.h>

// Problem constants
#define SEQ   4096
#define BS    4
#define SIZE  1024
#define NROWS (SEQ * BS)     // 16384
#define NDROP 409            // max(1, int(4096 * 0.1))

// Scratch (device globals; no allocation allowed)
__device__ float g_key[BS * SEQ];    // key[b][s] = gumbel - w
__device__ float g_mask[BS * SEQ];   // 1.0 keep, 0.0 drop

// ---------------------------------------------------------------------------
// K1: w[b,s] = dot(h[s,b,:], emb); key = gumbel(u) - w.  One warp per row.
// ---------------------------------------------------------------------------
__global__ void k_dot(const float* __restrict__ h,
                      const float* __restrict__ emb,
                      const float* __restrict__ gu)
{
    int gwarp = (blockIdx.x * blockDim.x + threadIdx.x) >> 5;
    int lane  = threadIdx.x & 31;
    if (gwarp >= NROWS) return;

    const float4* hr = reinterpret_cast<const float4*>(h + (size_t)gwarp * SIZE);
    const float4* e4 = reinterpret_cast<const float4*>(emb);

    float acc = 0.f;
    #pragma unroll
    for (int i = 0; i < 8; i++) {
        float4 a = __ldg(&hr[lane + i * 32]);
        float4 b = __ldg(&e4[lane + i * 32]);
        acc += a.x * b.x + a.y * b.y + a.z * b.z + a.w * b.w;
    }
    #pragma unroll
    for (int o = 16; o; o >>= 1) acc += __shfl_xor_sync(0xFFFFFFFFu, acc, o);

    if (lane == 0) {
        int s = gwarp >> 2;          // row = s*BS + b
        int b = gwarp & 3;
        float u = gu[b * SEQ + s];
        float gum = -logf(-logf(u + 1e-20f) + 1e-20f);
        g_key[b * SEQ + s] = gum - acc;
    }
}

// ---------------------------------------------------------------------------
// K2: per-batch byte-wise radix select of the 409th-largest key, then build
// mask; exact JAX tie-break (lowest index wins) fully in parallel.
// 1 block (512 threads) per batch. Thread t owns contiguous chunk [8t, 8t+8).
// ---------------------------------------------------------------------------
__global__ void k_select()
{
    __shared__ unsigned su[SEQ];       // 16 KB
    __shared__ int hist[256];
    __shared__ int tmp[256];           // suffix-scan workspace
    __shared__ int eq[512];            // per-chunk equal counts
    __shared__ int scn[512];           // scan workspace
    __shared__ int sh_k, sh_digit, sh_gt;

    const int b = blockIdx.x;
    const int t = threadIdx.x;         // 512

    // order-preserving float->uint map (ascending)
    #pragma unroll
    for (int j = 0; j < 8; j++) {
        int i = t * 8 + j;
        unsigned u = __float_as_uint(g_key[b * SEQ + i]);
        su[i] = (u & 0x80000000u) ? ~u : (u | 0x80000000u);
    }
    if (t == 0) sh_k = NDROP;
    __syncthreads();

    unsigned prefix = 0;
    unsigned himask = 0;               // bits already fixed
    #pragma unroll
    for (int pass = 0; pass < 4; pass++) {
        const int shift = 24 - 8 * pass;
        if (t < 256) hist[t] = 0;
        __syncthreads();
        const int k = sh_k;

        #pragma unroll
        for (int j = 0; j < 8; j++) {
            unsigned v = su[t * 8 + j];
            if ((v & himask) == prefix)
                atomicAdd(&hist[(v >> shift) & 255u], 1);
        }
        __syncthreads();

        // inclusive suffix sum of hist into tmp
        if (t < 256) tmp[t] = hist[t];
        __syncthreads();
        #pragma unroll
        for (int off = 1; off < 256; off <<= 1) {
            int v = 0;
            if (t < 256) { v = tmp[t]; if (t + off < 256) v += tmp[t + off]; }
            __syncthreads();
            if (t < 256) tmp[t] = v;
            __syncthreads();
        }
        // pick digit d: suffix(d) >= k > suffix(d+1)
        if (t < 256) {
            int sufNext = (t < 255) ? tmp[t + 1] : 0;
            if (tmp[t] >= k && sufNext < k) { sh_digit = t; sh_k = k - sufNext; }
        }
        __syncthreads();
        prefix |= ((unsigned)sh_digit) << shift;
        himask |= 0xFFu << shift;
        __syncthreads();
    }
    // prefix == mapped value of the 409th-largest key

    // per-chunk counts: strictly greater (total) and equal (for tie ranks)
    if (t == 0) sh_gt = 0;
    __syncthreads();
    int gtloc = 0, eqloc = 0;
    #pragma unroll
    for (int j = 0; j < 8; j++) {
        unsigned v = su[t * 8 + j];
        gtloc += (v > prefix);
        eqloc += (v == prefix);
    }
    eq[t] = eqloc;
    atomicAdd(&sh_gt, gtloc);
    __syncthreads();

    // exclusive scan of eq over 512 chunks (index order == chunk order)
    scn[t] = eqloc;
    __syncthreads();
    #pragma unroll
    for (int off = 1; off < 512; off <<= 1) {
        int v = scn[t] + ((t >= off) ? scn[t - off] : 0);
        __syncthreads();
        scn[t] = v;
        __syncthreads();
    }
    const int eqBefore = scn[t] - eqloc;
    const int need = NDROP - sh_gt;    // equals to drop, lowest index first

    int r = eqBefore;
    #pragma unroll
    for (int j = 0; j < 8; j++) {
        int i = t * 8 + j;
        unsigned v = su[i];
        float m;
        if (v > prefix)       m = 0.f;
        else if (v == prefix) { m = (r < need) ? 0.f : 1.f; r++; }
        else                  m = 1.f;
        g_mask[b * SEQ + i] = m;
    }
}

// ---------------------------------------------------------------------------
// K3: y = x + h*mask; LayerNorm(1024, eps=1e-12). One WARP per row, no
// barriers: 8 float4 per lane held in registers, shuffle reduction.
// ---------------------------------------------------------------------------
__global__ void k_ln(const float* __restrict__ x,
                     const float* __restrict__ h,
                     const float* __restrict__ gamma,
                     const float* __restrict__ beta,
                     float* __restrict__ out)
{
    const int w    = (blockIdx.x * blockDim.x + threadIdx.x) >> 5;  // row
    const int lane = threadIdx.x & 31;
    if (w >= NROWS) return;

    const int s = w >> 2;
    const int b = w & 3;
    const float m = g_mask[b * SEQ + s];

    const size_t base = (size_t)w * SIZE;
    const float4* x4 = reinterpret_cast<const float4*>(x + base);
    const float4* h4 = reinterpret_cast<const float4*>(h + base);

    float4 y[8];
    float sum = 0.f, sq = 0.f;
    #pragma unroll
    for (int i = 0; i < 8; i++) {
        float4 xv = __ldg(&x4[lane + 32 * i]);
        float4 hv = __ldg(&h4[lane + 32 * i]);
        y[i].x = xv.x + hv.x * m;
        y[i].y = xv.y + hv.y * m;
        y[i].z = xv.z + hv.z * m;
        y[i].w = xv.w + hv.w * m;
        sum += y[i].x + y[i].y + y[i].z + y[i].w;
        sq  += y[i].x * y[i].x + y[i].y * y[i].y
             + y[i].z * y[i].z + y[i].w * y[i].w;
    }
    #pragma unroll
    for (int o = 16; o; o >>= 1) {
        sum += __shfl_xor_sync(0xFFFFFFFFu, sum, o);
        sq  += __shfl_xor_sync(0xFFFFFFFFu, sq,  o);
    }
    const float mu   = sum * (1.f / SIZE);
    const float var  = sq * (1.f / SIZE) - mu * mu;
    const float rstd = rsqrtf(var + 1e-12f);

    const float4* g4 = reinterpret_cast<const float4*>(gamma);
    const float4* b4 = reinterpret_cast<const float4*>(beta);
    float4* o4 = reinterpret_cast<float4*>(out + base);
    #pragma unroll
    for (int i = 0; i < 8; i++) {
        float4 gv = __ldg(&g4[lane + 32 * i]);
        float4 bv = __ldg(&b4[lane + 32 * i]);
        float4 o;
        o.x = (y[i].x - mu) * rstd * gv.x + bv.x;
        o.y = (y[i].y - mu) * rstd * gv.y + bv.y;
        o.z = (y[i].z - mu) * rstd * gv.z + bv.z;
        o.w = (y[i].w - mu) * rstd * gv.w + bv.w;
        o4[lane + 32 * i] = o;
    }
}

// ---------------------------------------------------------------------------
extern "C" void kernel_launch(void* const* d_in, const int* in_sizes, int n_in,
                              void* d_out, int out_size)
{
    const float* x     = (const float*)d_in[0];  // (seq, bs, size)
    const float* h     = (const float*)d_in[1];  // (seq, bs, size)
    const float* emb   = (const float*)d_in[2];  // (size,)
    const float* gamma = (const float*)d_in[3];  // (size,)
    const float* beta  = (const float*)d_in[4];  // (size,)
    const float* gu    = (const float*)d_in[5];  // (bs, seq)
    // d_in[6] = lengths: unused by the reference
    float* out = (float*)d_out;

    k_dot<<<NROWS / 8, 256>>>(h, emb, gu);   // 8 warps/block
    k_select<<<BS, 512>>>();                 // 1 block per batch
    k_ln<<<NROWS / 8, 256>>>(x, h, gamma, beta, out);  // 1 warp per row
}

// round 3
// speedup vs baseline: 4.4307x; 1.0658x over previous
#include <cuda_runtime.h>
#include <cuda_bf16.h>
#include <stdint.h>

// Problem constants
#define SEQ   4096
#define BS    4
#define SIZE  1024
#define NROWS (SEQ * BS)     // 16384
#define NDROP 409            // max(1, int(4096 * 0.1))

// Scratch (device globals; no allocation allowed)
__device__ float g_key[BS * SEQ];    // key[b][s] = gumbel - w
__device__ float g_mask[BS * SEQ];   // 1.0 keep, 0.0 drop

// ---------------------------------------------------------------------------
// K1: w[b,s] = dot(h[s,b,:], emb); key = gumbel(u) - w.
// 2 rows per warp (16 DRAM loads in flight per lane), emb staged in smem.
// ---------------------------------------------------------------------------
__global__ void __launch_bounds__(256)
k_dot(const float* __restrict__ h,
      const float* __restrict__ emb,
      const float* __restrict__ gu)
{
    __shared__ float4 se[256];           // emb: 1024 floats = 4 KB

    const int t = threadIdx.x;
    se[t] = __ldg(&reinterpret_cast<const float4*>(emb)[t]);
    __syncthreads();

    const int warp  = t >> 5;
    const int lane  = t & 31;
    const int row0  = (blockIdx.x * 8 + warp) * 2;   // 2 consecutive rows
    if (row0 >= NROWS) return;

    const float4* h0 = reinterpret_cast<const float4*>(h + (size_t)row0 * SIZE);
    const float4* h1 = reinterpret_cast<const float4*>(h + (size_t)(row0 + 1) * SIZE);

    float acc0 = 0.f, acc1 = 0.f;
    #pragma unroll
    for (int i = 0; i < 8; i++) {
        float4 e = se[lane + i * 32];
        float4 a = __ldg(&h0[lane + i * 32]);
        float4 b = __ldg(&h1[lane + i * 32]);
        acc0 += a.x * e.x + a.y * e.y + a.z * e.z + a.w * e.w;
        acc1 += b.x * e.x + b.y * e.y + b.z * e.z + b.w * e.w;
    }
    #pragma unroll
    for (int o = 16; o; o >>= 1) {
        acc0 += __shfl_xor_sync(0xFFFFFFFFu, acc0, o);
        acc1 += __shfl_xor_sync(0xFFFFFFFFu, acc1, o);
    }

    if (lane < 2) {
        const int r   = row0 + lane;
        const float a = (lane == 0) ? acc0 : acc1;
        const int s   = r >> 2;
        const int b   = r & 3;
        float u = __ldg(&gu[b * SEQ + s]);
        float gum = -logf(-logf(u + 1e-20f) + 1e-20f);
        g_key[b * SEQ + s] = gum - a;
    }
}

// ---------------------------------------------------------------------------
// K2: per-batch byte-wise radix select of the 409th-largest key, then build
// mask; exact JAX tie-break (lowest index wins) fully in parallel.
// 1 block (512 threads) per batch. Thread t owns contiguous chunk [8t, 8t+8).
// ---------------------------------------------------------------------------
__global__ void k_select()
{
    __shared__ unsigned su[SEQ];       // 16 KB
    __shared__ int hist[256];
    __shared__ int tmp[256];
    __shared__ int scn[512];
    __shared__ int sh_k, sh_digit, sh_gt;

    const int b = blockIdx.x;
    const int t = threadIdx.x;         // 512

    #pragma unroll
    for (int j = 0; j < 8; j++) {
        int i = t * 8 + j;
        unsigned u = __float_as_uint(g_key[b * SEQ + i]);
        su[i] = (u & 0x80000000u) ? ~u : (u | 0x80000000u);
    }
    if (t == 0) sh_k = NDROP;
    __syncthreads();

    unsigned prefix = 0;
    unsigned himask = 0;
    #pragma unroll
    for (int pass = 0; pass < 4; pass++) {
        const int shift = 24 - 8 * pass;
        if (t < 256) hist[t] = 0;
        __syncthreads();
        const int k = sh_k;

        #pragma unroll
        for (int j = 0; j < 8; j++) {
            unsigned v = su[t * 8 + j];
            if ((v & himask) == prefix)
                atomicAdd(&hist[(v >> shift) & 255u], 1);
        }
        __syncthreads();

        if (t < 256) tmp[t] = hist[t];
        __syncthreads();
        #pragma unroll
        for (int off = 1; off < 256; off <<= 1) {
            int v = 0;
            if (t < 256) { v = tmp[t]; if (t + off < 256) v += tmp[t + off]; }
            __syncthreads();
            if (t < 256) tmp[t] = v;
            __syncthreads();
        }
        if (t < 256) {
            int sufNext = (t < 255) ? tmp[t + 1] : 0;
            if (tmp[t] >= k && sufNext < k) { sh_digit = t; sh_k = k - sufNext; }
        }
        __syncthreads();
        prefix |= ((unsigned)sh_digit) << shift;
        himask |= 0xFFu << shift;
        __syncthreads();
    }

    if (t == 0) sh_gt = 0;
    __syncthreads();
    int gtloc = 0, eqloc = 0;
    #pragma unroll
    for (int j = 0; j < 8; j++) {
        unsigned v = su[t * 8 + j];
        gtloc += (v > prefix);
        eqloc += (v == prefix);
    }
    atomicAdd(&sh_gt, gtloc);
    scn[t] = eqloc;
    __syncthreads();
    #pragma unroll
    for (int off = 1; off < 512; off <<= 1) {
        int v = scn[t] + ((t >= off) ? scn[t - off] : 0);
        __syncthreads();
        scn[t] = v;
        __syncthreads();
    }
    const int eqBefore = scn[t] - eqloc;
    const int need = NDROP - sh_gt;

    int r = eqBefore;
    #pragma unroll
    for (int j = 0; j < 8; j++) {
        int i = t * 8 + j;
        unsigned v = su[i];
        float m;
        if (v > prefix)       m = 0.f;
        else if (v == prefix) { m = (r < need) ? 0.f : 1.f; r++; }
        else                  m = 1.f;
        g_mask[b * SEQ + i] = m;
    }
}

// ---------------------------------------------------------------------------
// K3: y = x + h*mask; LayerNorm(1024, eps=1e-12).
// 2 warps per row (half row per warp, y[4] in regs -> lower reg pressure,
// higher occupancy). 256-thr blocks = 4 rows/block.
// ---------------------------------------------------------------------------
__global__ void __launch_bounds__(256)
k_ln(const float* __restrict__ x,
     const float* __restrict__ h,
     const float* __restrict__ gamma,
     const float* __restrict__ beta,
     float* __restrict__ out)
{
    __shared__ float red[16];            // [warp]=sum, [8+warp]=sq

    const int t    = threadIdx.x;
    const int warp = t >> 5;             // 0..7
    const int lane = t & 31;
    const int row  = blockIdx.x * 4 + (warp >> 1);
    const int half = warp & 1;

    const int s = row >> 2;
    const int b = row & 3;
    const float m = g_mask[b * SEQ + s];

    const size_t base = (size_t)row * SIZE;
    const int fo = half * 128 + lane;    // float4 index base within row
    const float4* x4 = reinterpret_cast<const float4*>(x + base);
    const float4* h4 = reinterpret_cast<const float4*>(h + base);

    float4 y[4];
    float sum = 0.f, sq = 0.f;
    #pragma unroll
    for (int i = 0; i < 4; i++) {
        float4 xv = __ldg(&x4[fo + 32 * i]);
        float4 hv = __ldg(&h4[fo + 32 * i]);
        y[i].x = xv.x + hv.x * m;
        y[i].y = xv.y + hv.y * m;
        y[i].z = xv.z + hv.z * m;
        y[i].w = xv.w + hv.w * m;
        sum += y[i].x + y[i].y + y[i].z + y[i].w;
        sq  += y[i].x * y[i].x + y[i].y * y[i].y
             + y[i].z * y[i].z + y[i].w * y[i].w;
    }
    #pragma unroll
    for (int o = 16; o; o >>= 1) {
        sum += __shfl_xor_sync(0xFFFFFFFFu, sum, o);
        sq  += __shfl_xor_sync(0xFFFFFFFFu, sq,  o);
    }
    if (lane == 0) { red[warp] = sum; red[8 + warp] = sq; }
    __syncthreads();

    const int wpair = warp & ~1;
    const float S = red[wpair] + red[wpair + 1];
    const float Q = red[8 + wpair] + red[8 + wpair + 1];
    const float mu   = S * (1.f / SIZE);
    const float var  = Q * (1.f / SIZE) - mu * mu;
    const float rstd = rsqrtf(var + 1e-12f);

    const float4* g4 = reinterpret_cast<const float4*>(gamma);
    const float4* b4 = reinterpret_cast<const float4*>(beta);
    float4* o4 = reinterpret_cast<float4*>(out + base);
    #pragma unroll
    for (int i = 0; i < 4; i++) {
        float4 gv = __ldg(&g4[fo + 32 * i]);
        float4 bv = __ldg(&b4[fo + 32 * i]);
        float4 o;
        o.x = (y[i].x - mu) * rstd * gv.x + bv.x;
        o.y = (y[i].y - mu) * rstd * gv.y + bv.y;
        o.z = (y[i].z - mu) * rstd * gv.z + bv.z;
        o.w = (y[i].w - mu) * rstd * gv.w + bv.w;
        o4[fo + 32 * i] = o;
    }
}

// ---------------------------------------------------------------------------
extern "C" void kernel_launch(void* const* d_in, const int* in_sizes, int n_in,
                              void* d_out, int out_size)
{
    const float* x     = (const float*)d_in[0];
    const float* h     = (const float*)d_in[1];
    const float* emb   = (const float*)d_in[2];
    const float* gamma = (const float*)d_in[3];
    const float* beta  = (const float*)d_in[4];
    const float* gu    = (const float*)d_in[5];
    // d_in[6] = lengths: unused by the reference
    float* out = (float*)d_out;

    k_dot<<<NROWS / 16, 256>>>(h, emb, gu);            // 2 rows/warp
    k_select<<<BS, 512>>>();                           // 1 block per batch
    k_ln<<<NROWS / 4, 256>>>(x, h, gamma, beta, out);  // 2 warps/row
}